// round 5
// baseline (speedup 1.0000x reference)
#include <cuda_runtime.h>
#include <math.h>

// Problem constants
static constexpr int NB = 8, NC = 256, NH = 128, NW = 128;
static constexpr int HW = NH * NW;
static constexpr float EPSF = 1e-8f;

static constexpr int CSPLIT = 4;          // channel slices
static constexpr int CPG = NC / CSPLIT;   // 64 channels per block
static constexpr int NSTRIP = 32;         // epilogue strips (4 rows each)

typedef unsigned long long ull;

// Device scratch (dense writes only; every element written each run)
__device__ float g_dots[CSPLIT][(size_t)NB * HW * 12];  // [(b*HW+p)*12 + d]
__device__ float g_nsq [CSPLIT][NB * HW];
__device__ float g_stotal[NB * NSTRIP];
__device__ int   g_scnt [NB * NSTRIP];
__device__ int   g_sinc [NB * NSTRIP];
__device__ int   g_arrive;                // zero-init; reset by last block

__device__ __forceinline__ ull pk(float lo, float hi) {
    ull r;
    asm("mov.b64 %0, {%1, %2};" : "=l"(r) : "f"(lo), "f"(hi));
    return r;
}
__device__ __forceinline__ void upk(ull v, float& lo, float& hi) {
    asm("mov.b64 {%0, %1}, %2;" : "=f"(lo), "=f"(hi) : "l"(v));
}
__device__ __forceinline__ void fma2(ull& a, ull x, ull y) {
    asm("fma.rn.f32x2 %0, %1, %2, %0;" : "+l"(a) : "l"(x), "l"(y));
}

// ---------------------------------------------------------------------------
// Kernel 1: partial dots + norm^2. SMEM-free, f32x2, double-buffered prefetch.
// Block = 128 threads = 4 rows x 128 cols (4 px/thread). Grid = (32, NB, 4).
// ---------------------------------------------------------------------------
__global__ __launch_bounds__(128, 4) void partial_kernel(const float* __restrict__ er)
{
    const int b   = blockIdx.y;
    const int cs  = blockIdx.z;
    const int tid = threadIdx.x;
    const int y   = blockIdx.x * 4 + (tid >> 5);
    const int x0  = (tid & 31) * 4;

    const float* plane = er + ((size_t)b * NC + cs * CPG) * HW;

    // Relative offsets (upper clamps keep alignment; garbage is weight-0 downstream)
    const int rB0 = y * NW + x0;
    const int rD0 = min(rB0 + 4,          HW - 2);
    const int rA1 = min(rB0 + NW - 2,     HW - 2);
    const int rB1 = min(rB0 + NW,         HW - 4);
    const int rD1 = min(rB0 + NW + 4,     HW - 2);
    const int rA2 = min(rB0 + 2 * NW - 2, HW - 2);
    const int rB2 = min(rB0 + 2 * NW,     HW - 4);
    const int rD2 = min(rB0 + 2 * NW + 4, HW - 2);

    // Double-buffered register windows
    float4 B0[2], B1[2], B2[2];
    float2 D0[2], A1[2], D1[2], A2[2], D2[2];

#define LOADW(buf, base) {                                                \
        const float* _p = (base);                                        \
        B0[buf] = *(const float4*)(_p + rB0);                            \
        D0[buf] = *(const float2*)(_p + rD0);                            \
        A1[buf] = *(const float2*)(_p + rA1);                            \
        B1[buf] = *(const float4*)(_p + rB1);                            \
        D1[buf] = *(const float2*)(_p + rD1);                            \
        A2[buf] = *(const float2*)(_p + rA2);                            \
        B2[buf] = *(const float4*)(_p + rB2);                            \
        D2[buf] = *(const float2*)(_p + rD2);                            \
    }

    ull a0[12], a1[12];
#pragma unroll
    for (int d = 0; d < 12; d++) { a0[d] = 0ull; a1[d] = 0ull; }
    ull self0 = 0ull, self1 = 0ull;

    LOADW(0, plane);

#pragma unroll 1
    for (int c = 0; c < CPG; c++) {
        const int cur = c & 1;
        const int nxt = cur ^ 1;
        if (c + 1 < CPG) LOADW(nxt, plane + (size_t)(c + 1) * HW);

        const float4 b0 = B0[cur], b1 = B1[cur], b2 = B2[cur];
        const float2 d0v = D0[cur], a1v = A1[cur], d1v = D1[cur];
        const float2 a2v = A2[cur], d2v = D2[cur];

        // row 0 pairs (start dx 0..4)
        ull p0 = pk(b0.x, b0.y), p1 = pk(b0.y, b0.z), p2 = pk(b0.z, b0.w);
        ull p3 = pk(b0.w, d0v.x), p4 = pk(d0v.x, d0v.y);
        fma2(self0, p0, p0);
        fma2(self1, p2, p2);
        fma2(a0[0], p0, p1);  fma2(a1[0], p2, p3);
        fma2(a0[1], p0, p2);  fma2(a1[1], p2, p4);

        // row 1 pairs (start dx -2..4); d = 2..6
        ull q0 = pk(a1v.x, a1v.y), q1 = pk(a1v.y, b1.x), q2 = pk(b1.x, b1.y);
        ull q3 = pk(b1.y, b1.z),  q4 = pk(b1.z, b1.w), q5 = pk(b1.w, d1v.x);
        ull q6 = pk(d1v.x, d1v.y);
        fma2(a0[2], p0, q0); fma2(a0[3], p0, q1); fma2(a0[4], p0, q2);
        fma2(a0[5], p0, q3); fma2(a0[6], p0, q4);
        fma2(a1[2], p2, q2); fma2(a1[3], p2, q3); fma2(a1[4], p2, q4);
        fma2(a1[5], p2, q5); fma2(a1[6], p2, q6);

        // row 2 pairs; d = 7..11
        ull r0 = pk(a2v.x, a2v.y), r1 = pk(a2v.y, b2.x), r2 = pk(b2.x, b2.y);
        ull r3 = pk(b2.y, b2.z),  r4 = pk(b2.z, b2.w), r5 = pk(b2.w, d2v.x);
        ull r6 = pk(d2v.x, d2v.y);
        fma2(a0[7],  p0, r0); fma2(a0[8],  p0, r1); fma2(a0[9],  p0, r2);
        fma2(a0[10], p0, r3); fma2(a0[11], p0, r4);
        fma2(a1[7],  p2, r2); fma2(a1[8],  p2, r3); fma2(a1[9],  p2, r4);
        fma2(a1[10], p2, r5); fma2(a1[11], p2, r6);
    }
#undef LOADW

    // --- writeback ---
    const int p00 = y * NW + x0;
    float* dbase = g_dots[cs] + (size_t)b * HW * 12;
    float v0[12], v1[12], v2[12], v3[12];
#pragma unroll
    for (int d = 0; d < 12; d++) {
        upk(a0[d], v0[d], v1[d]);
        upk(a1[d], v2[d], v3[d]);
    }
#define ST12(P, V) {                                                      \
        float4* dst = (float4*)(dbase + (size_t)(P) * 12);                \
        dst[0] = make_float4(V[0], V[1], V[2],  V[3]);                    \
        dst[1] = make_float4(V[4], V[5], V[6],  V[7]);                    \
        dst[2] = make_float4(V[8], V[9], V[10], V[11]);                   \
    }
    ST12(p00,     v0);
    ST12(p00 + 1, v1);
    ST12(p00 + 2, v2);
    ST12(p00 + 3, v3);
#undef ST12
    float s0, s1, s2, s3;
    upk(self0, s0, s1);
    upk(self1, s2, s3);
    *(float4*)(g_nsq[cs] + b * HW + p00) = make_float4(s0, s1, s2, s3);
}

// ---------------------------------------------------------------------------
// Kernel 2: epilogue + fused finalize. Block = (4-row strip, image), 512 thr.
// ---------------------------------------------------------------------------
__global__ __launch_bounds__(512) void epilogue_kernel(
    const int* __restrict__ seg, const int* __restrict__ gtb,
    float* __restrict__ out)
{
    __shared__ float shN[8 * 132];
    __shared__ int   shL[8 * 132];
    __shared__ float sRf[16];
    __shared__ int   sRc[16], sRi[16];
    __shared__ int   sLast;

    const int strip = blockIdx.x;
    const int b     = blockIdx.y;
    const int h0    = strip * 4;
    const int tid   = threadIdx.x;
    const int* segb = seg + b * HW;
    const int* gtbb = gtb + b * HW;

    // Stage norms + label codes for rows [h0-2, h0+6), cols [-2, 130)
    for (int i = tid; i < 8 * 132; i += 512) {
        int r = i / 132, c = i - r * 132;
        int gh = h0 - 2 + r, gw = c - 2;
        float nrm = 1.f;
        int code = 0x7FFF;
        if (gh >= 0 && gh < NH && gw >= 0 && gw < NW) {
            int idx = b * HW + gh * NW + gw;
            float ns = g_nsq[0][idx] + g_nsq[1][idx] + g_nsq[2][idx] + g_nsq[3][idx];
            nrm = fmaxf(sqrtf(ns), EPSF);
            int li = gh * NW + gw;
            int s = segb[li], g = gtbb[li];
            int s0 = (s == 255) ? 0 : s;
            int g0 = (g == 255) ? 0 : g;
            bool fg    = (s0 * g0 > 0);
            bool inter = (gh >= 2 && gh < NH - 2 && gw >= 2 && gw < NW - 2);
            code = (s & 0xFFFF) | ((fg && inter) ? 0x10000 : 0) | (fg ? 0x20000 : 0);
        }
        shN[i] = nrm;
        shL[i] = code;
    }
    __syncthreads();

    const int ty = tid >> 7, tx = tid & 127;
    const int p  = (h0 + ty) * NW + tx;

    // Sum the 4 slice dot-partials
    float dsum[12];
    {
        const size_t off = ((size_t)b * HW + p) * 12;
        float4 a0, a1, a2;
        {
            const float4* s = (const float4*)(g_dots[0] + off);
            a0 = s[0]; a1 = s[1]; a2 = s[2];
        }
#pragma unroll
        for (int cs = 1; cs < CSPLIT; cs++) {
            const float4* s = (const float4*)(g_dots[cs] + off);
            float4 t0 = s[0], t1 = s[1], t2 = s[2];
            a0.x += t0.x; a0.y += t0.y; a0.z += t0.z; a0.w += t0.w;
            a1.x += t1.x; a1.y += t1.y; a1.z += t1.z; a1.w += t1.w;
            a2.x += t2.x; a2.y += t2.y; a2.z += t2.z; a2.w += t2.w;
        }
        dsum[0] = a0.x; dsum[1] = a0.y; dsum[2]  = a0.z; dsum[3]  = a0.w;
        dsum[4] = a1.x; dsum[5] = a1.y; dsum[6]  = a1.z; dsum[7]  = a1.w;
        dsum[8] = a2.x; dsum[9] = a2.y; dsum[10] = a2.z; dsum[11] = a2.w;
    }

    const int mp = (ty + 2) * 132 + (tx + 2);
    const int dof[12] = {1, 2,
                         132 - 2, 132 - 1, 132, 132 + 1, 132 + 2,
                         264 - 2, 264 - 1, 264, 264 + 1, 264 + 2};

    int pcode = shL[mp];
    float vp  = (float)((pcode >> 16) & 1);
    int   cnt = (pcode >> 16) & 1;
    int   inc = (pcode >> 17) & 1;
    int   sp  = pcode & 0xFFFF;
    float np  = shN[mp];

    float acc = 0.f;
#pragma unroll
    for (int d = 0; d < 12; d++) {
        int ncode = shL[mp + dof[d]];
        float vn  = (float)((ncode >> 16) & 1);
        float wgt = vp + vn;
        float nn  = shN[mp + dof[d]];
        float cosv = dsum[d] / (np * nn);
        int sn = ncode & 0xFFFF;
        float lab = (sp == sn && sp < 2) ? 1.f : 0.f;
        float diff = cosv - lab;
        acc += wgt * diff * diff;
    }

    // Block reduce (16 warps)
    unsigned mask = 0xFFFFFFFFu;
#pragma unroll
    for (int off = 16; off > 0; off >>= 1) {
        acc += __shfl_down_sync(mask, acc, off);
        cnt += __shfl_down_sync(mask, cnt, off);
        inc |= __shfl_down_sync(mask, inc, off);
    }
    if ((tid & 31) == 0) { sRf[tid >> 5] = acc; sRc[tid >> 5] = cnt; sRi[tid >> 5] = inc; }
    __syncthreads();
    if (tid < 32) {
        float a = (tid < 16) ? sRf[tid] : 0.f;
        int   c = (tid < 16) ? sRc[tid] : 0;
        int   i = (tid < 16) ? sRi[tid] : 0;
#pragma unroll
        for (int off = 8; off > 0; off >>= 1) {
            a += __shfl_down_sync(mask, a, off);
            c += __shfl_down_sync(mask, c, off);
            i |= __shfl_down_sync(mask, i, off);
        }
        if (tid == 0) {
            g_stotal[b * NSTRIP + strip] = a;
            g_scnt [b * NSTRIP + strip] = c;
            g_sinc [b * NSTRIP + strip] = i;
            __threadfence();
            int t = atomicAdd(&g_arrive, 1);
            sLast = (t == NB * NSTRIP - 1) ? 1 : 0;
        }
    }
    __syncthreads();

    // Fused finalize: last block computes the scalar loss.
    if (sLast && tid < NB) {
        float tot = 0.f; int c = 0, i = 0;
        for (int s = 0; s < NSTRIP; s++) {
            tot += g_stotal[tid * NSTRIP + s];
            c   += g_scnt [tid * NSTRIP + s];
            i   |= g_sinc [tid * NSTRIP + s];
        }
        float li = i ? (tot / fmaxf((float)c, 1.f) / 24.f) : 0.f;
        unsigned m8 = 0xFFu;
        int sn = i ? 1 : 0;
#pragma unroll
        for (int off = 4; off > 0; off >>= 1) {
            li += __shfl_down_sync(m8, li, off);
            sn += __shfl_down_sync(m8, sn, off);
        }
        if (tid == 0) {
            out[0] = li / (float)(sn > 0 ? sn : 1);
            g_arrive = 0;   // reset for next graph replay
        }
    }
}

extern "C" void kernel_launch(void* const* d_in, const int* in_sizes, int n_in,
                              void* d_out, int out_size) {
    const float* er  = (const float*)d_in[0];
    const int*   seg = (const int*)d_in[1];
    const int*   gtb = (const int*)d_in[2];

    dim3 gridP(NH / 4, NB, CSPLIT);     // 32 x 8 x 4 = 1024 blocks
    partial_kernel<<<gridP, 128>>>(er);
    dim3 gridE(NSTRIP, NB);             // 32 x 8 = 256 blocks
    epilogue_kernel<<<gridE, 512>>>(seg, gtb, (float*)d_out);
}

// round 6
// speedup vs baseline: 1.7398x; 1.7398x over previous
#include <cuda_runtime.h>
#include <math.h>

// Problem constants
static constexpr int NB = 8, NC = 256, NH = 128, NW = 128;
static constexpr int HW = NH * NW;
static constexpr float EPSF = 1e-8f;

static constexpr int CSPLIT = 4;          // channel slices
static constexpr int CPG = NC / CSPLIT;   // 64 channels per block
static constexpr int NSTRIP = 32;         // epilogue strips (4 rows each)

typedef unsigned long long ull;

// Device scratch (dense writes only; every element written each run)
__device__ float g_dots[CSPLIT][(size_t)NB * HW * 12];  // [(b*HW+p)*12 + d]
__device__ float g_nsq [CSPLIT][NB * HW];
__device__ float g_stotal[NB * NSTRIP];
__device__ int   g_scnt [NB * NSTRIP];
__device__ int   g_sinc [NB * NSTRIP];
__device__ int   g_arrive;                // zero-init; reset by last block

__device__ __forceinline__ ull pk(float lo, float hi) {
    ull r;
    asm("mov.b64 %0, {%1, %2};" : "=l"(r) : "f"(lo), "f"(hi));
    return r;
}
__device__ __forceinline__ void upk(ull v, float& lo, float& hi) {
    asm("mov.b64 {%0, %1}, %2;" : "=f"(lo), "=f"(hi) : "l"(v));
}
__device__ __forceinline__ void fma2(ull& a, ull x, ull y) {
    asm("fma.rn.f32x2 %0, %1, %2, %0;" : "+l"(a) : "l"(x), "l"(y));
}

// Register window: named members only (never indexed dynamically -> stays in regs)
struct Win {
    float4 B0, B1, B2;
    float2 D0, A1, D1, A2, D2;
};

// ---------------------------------------------------------------------------
// Kernel 1: partial dots + norm^2. SMEM-free, f32x2, explicit 2-stage pipeline.
// Block = 128 threads = 4 rows x 128 cols (4 px/thread). Grid = (32, NB, 4).
// ---------------------------------------------------------------------------
__global__ __launch_bounds__(128, 3) void partial_kernel(const float* __restrict__ er)
{
    const int b   = blockIdx.y;
    const int cs  = blockIdx.z;
    const int tid = threadIdx.x;
    const int y   = blockIdx.x * 4 + (tid >> 5);
    const int x0  = (tid & 31) * 4;

    const float* plane = er + ((size_t)b * NC + cs * CPG) * HW;

    // Relative offsets (upper clamps keep alignment; garbage is weight-0 downstream)
    const int rB0 = y * NW + x0;
    const int rD0 = min(rB0 + 4,          HW - 2);
    const int rA1 = min(rB0 + NW - 2,     HW - 2);
    const int rB1 = min(rB0 + NW,         HW - 4);
    const int rD1 = min(rB0 + NW + 4,     HW - 2);
    const int rA2 = min(rB0 + 2 * NW - 2, HW - 2);
    const int rB2 = min(rB0 + 2 * NW,     HW - 4);
    const int rD2 = min(rB0 + 2 * NW + 4, HW - 2);

#define LOADW(W, CIDX) {                                                  \
        const float* _p = plane + (size_t)(CIDX) * HW;                    \
        (W).B0 = *(const float4*)(_p + rB0);                              \
        (W).D0 = *(const float2*)(_p + rD0);                              \
        (W).A1 = *(const float2*)(_p + rA1);                              \
        (W).B1 = *(const float4*)(_p + rB1);                              \
        (W).D1 = *(const float2*)(_p + rD1);                              \
        (W).A2 = *(const float2*)(_p + rA2);                              \
        (W).B2 = *(const float4*)(_p + rB2);                              \
        (W).D2 = *(const float2*)(_p + rD2);                              \
    }

    ull a0[12], a1[12];
#pragma unroll
    for (int d = 0; d < 12; d++) { a0[d] = 0ull; a1[d] = 0ull; }
    ull self0 = 0ull, self1 = 0ull;

#define COMPUTE(W) {                                                      \
        const float4 b0 = (W).B0, b1v = (W).B1, b2v = (W).B2;             \
        const float2 d0v = (W).D0, a1v = (W).A1, d1v = (W).D1;            \
        const float2 a2v = (W).A2, d2v = (W).D2;                          \
        /* row 0 pairs (start dx 0..4) */                                 \
        ull p0 = pk(b0.x, b0.y), p1 = pk(b0.y, b0.z), p2 = pk(b0.z, b0.w);\
        ull p3 = pk(b0.w, d0v.x), p4 = pk(d0v.x, d0v.y);                  \
        fma2(self0, p0, p0);                                              \
        fma2(self1, p2, p2);                                              \
        fma2(a0[0], p0, p1);  fma2(a1[0], p2, p3);                        \
        fma2(a0[1], p0, p2);  fma2(a1[1], p2, p4);                        \
        /* row 1 pairs (start dx -2..4); d = 2..6 */                      \
        ull q0 = pk(a1v.x, a1v.y), q1 = pk(a1v.y, b1v.x);                 \
        ull q2 = pk(b1v.x, b1v.y), q3 = pk(b1v.y, b1v.z);                 \
        ull q4 = pk(b1v.z, b1v.w), q5 = pk(b1v.w, d1v.x);                 \
        ull q6 = pk(d1v.x, d1v.y);                                        \
        fma2(a0[2], p0, q0); fma2(a0[3], p0, q1); fma2(a0[4], p0, q2);    \
        fma2(a0[5], p0, q3); fma2(a0[6], p0, q4);                         \
        fma2(a1[2], p2, q2); fma2(a1[3], p2, q3); fma2(a1[4], p2, q4);    \
        fma2(a1[5], p2, q5); fma2(a1[6], p2, q6);                         \
        /* row 2 pairs; d = 7..11 */                                      \
        ull r0 = pk(a2v.x, a2v.y), r1 = pk(a2v.y, b2v.x);                 \
        ull r2 = pk(b2v.x, b2v.y), r3 = pk(b2v.y, b2v.z);                 \
        ull r4 = pk(b2v.z, b2v.w), r5 = pk(b2v.w, d2v.x);                 \
        ull r6 = pk(d2v.x, d2v.y);                                        \
        fma2(a0[7],  p0, r0); fma2(a0[8],  p0, r1); fma2(a0[9],  p0, r2); \
        fma2(a0[10], p0, r3); fma2(a0[11], p0, r4);                       \
        fma2(a1[7],  p2, r2); fma2(a1[8],  p2, r3); fma2(a1[9],  p2, r4); \
        fma2(a1[10], p2, r5); fma2(a1[11], p2, r6);                       \
    }

    Win win0, win1;
    LOADW(win0, 0);

#pragma unroll 1
    for (int c = 0; c < CPG; c += 2) {
        LOADW(win1, c + 1);          // prefetch odd channel
        COMPUTE(win0);
        if (c + 2 < CPG) LOADW(win0, c + 2);   // prefetch next even channel
        COMPUTE(win1);
    }
#undef LOADW
#undef COMPUTE

    // --- writeback ---
    const int p00 = y * NW + x0;
    float* dbase = g_dots[cs] + (size_t)b * HW * 12;
    float v0[12], v1[12], v2[12], v3[12];
#pragma unroll
    for (int d = 0; d < 12; d++) {
        upk(a0[d], v0[d], v1[d]);
        upk(a1[d], v2[d], v3[d]);
    }
#define ST12(P, V) {                                                      \
        float4* dst = (float4*)(dbase + (size_t)(P) * 12);                \
        dst[0] = make_float4(V[0], V[1], V[2],  V[3]);                    \
        dst[1] = make_float4(V[4], V[5], V[6],  V[7]);                    \
        dst[2] = make_float4(V[8], V[9], V[10], V[11]);                   \
    }
    ST12(p00,     v0);
    ST12(p00 + 1, v1);
    ST12(p00 + 2, v2);
    ST12(p00 + 3, v3);
#undef ST12
    float s0, s1, s2, s3;
    upk(self0, s0, s1);
    upk(self1, s2, s3);
    *(float4*)(g_nsq[cs] + b * HW + p00) = make_float4(s0, s1, s2, s3);
}

// ---------------------------------------------------------------------------
// Kernel 2: epilogue + fused finalize. Block = (4-row strip, image), 512 thr.
// ---------------------------------------------------------------------------
__global__ __launch_bounds__(512) void epilogue_kernel(
    const int* __restrict__ seg, const int* __restrict__ gtb,
    float* __restrict__ out)
{
    __shared__ float shN[8 * 132];
    __shared__ int   shL[8 * 132];
    __shared__ float sRf[16];
    __shared__ int   sRc[16], sRi[16];
    __shared__ int   sLast;

    const int strip = blockIdx.x;
    const int b     = blockIdx.y;
    const int h0    = strip * 4;
    const int tid   = threadIdx.x;
    const int* segb = seg + b * HW;
    const int* gtbb = gtb + b * HW;

    // Stage norms + label codes for rows [h0-2, h0+6), cols [-2, 130)
    for (int i = tid; i < 8 * 132; i += 512) {
        int r = i / 132, c = i - r * 132;
        int gh = h0 - 2 + r, gw = c - 2;
        float nrm = 1.f;
        int code = 0x7FFF;
        if (gh >= 0 && gh < NH && gw >= 0 && gw < NW) {
            int idx = b * HW + gh * NW + gw;
            float ns = g_nsq[0][idx] + g_nsq[1][idx] + g_nsq[2][idx] + g_nsq[3][idx];
            nrm = fmaxf(sqrtf(ns), EPSF);
            int li = gh * NW + gw;
            int s = segb[li], g = gtbb[li];
            int s0 = (s == 255) ? 0 : s;
            int g0 = (g == 255) ? 0 : g;
            bool fg    = (s0 * g0 > 0);
            bool inter = (gh >= 2 && gh < NH - 2 && gw >= 2 && gw < NW - 2);
            code = (s & 0xFFFF) | ((fg && inter) ? 0x10000 : 0) | (fg ? 0x20000 : 0);
        }
        shN[i] = nrm;
        shL[i] = code;
    }
    __syncthreads();

    const int ty = tid >> 7, tx = tid & 127;
    const int p  = (h0 + ty) * NW + tx;

    // Sum the 4 slice dot-partials
    float dsum[12];
    {
        const size_t off = ((size_t)b * HW + p) * 12;
        float4 a0, a1, a2;
        {
            const float4* s = (const float4*)(g_dots[0] + off);
            a0 = s[0]; a1 = s[1]; a2 = s[2];
        }
#pragma unroll
        for (int cs = 1; cs < CSPLIT; cs++) {
            const float4* s = (const float4*)(g_dots[cs] + off);
            float4 t0 = s[0], t1 = s[1], t2 = s[2];
            a0.x += t0.x; a0.y += t0.y; a0.z += t0.z; a0.w += t0.w;
            a1.x += t1.x; a1.y += t1.y; a1.z += t1.z; a1.w += t1.w;
            a2.x += t2.x; a2.y += t2.y; a2.z += t2.z; a2.w += t2.w;
        }
        dsum[0] = a0.x; dsum[1] = a0.y; dsum[2]  = a0.z; dsum[3]  = a0.w;
        dsum[4] = a1.x; dsum[5] = a1.y; dsum[6]  = a1.z; dsum[7]  = a1.w;
        dsum[8] = a2.x; dsum[9] = a2.y; dsum[10] = a2.z; dsum[11] = a2.w;
    }

    const int mp = (ty + 2) * 132 + (tx + 2);
    const int dof[12] = {1, 2,
                         132 - 2, 132 - 1, 132, 132 + 1, 132 + 2,
                         264 - 2, 264 - 1, 264, 264 + 1, 264 + 2};

    int pcode = shL[mp];
    float vp  = (float)((pcode >> 16) & 1);
    int   cnt = (pcode >> 16) & 1;
    int   inc = (pcode >> 17) & 1;
    int   sp  = pcode & 0xFFFF;
    float np  = shN[mp];

    float acc = 0.f;
#pragma unroll
    for (int d = 0; d < 12; d++) {
        int ncode = shL[mp + dof[d]];
        float vn  = (float)((ncode >> 16) & 1);
        float wgt = vp + vn;
        float nn  = shN[mp + dof[d]];
        float cosv = dsum[d] / (np * nn);
        int sn = ncode & 0xFFFF;
        float lab = (sp == sn && sp < 2) ? 1.f : 0.f;
        float diff = cosv - lab;
        acc += wgt * diff * diff;
    }

    // Block reduce (16 warps)
    unsigned mask = 0xFFFFFFFFu;
#pragma unroll
    for (int off = 16; off > 0; off >>= 1) {
        acc += __shfl_down_sync(mask, acc, off);
        cnt += __shfl_down_sync(mask, cnt, off);
        inc |= __shfl_down_sync(mask, inc, off);
    }
    if ((tid & 31) == 0) { sRf[tid >> 5] = acc; sRc[tid >> 5] = cnt; sRi[tid >> 5] = inc; }
    __syncthreads();
    if (tid < 32) {
        float a = (tid < 16) ? sRf[tid] : 0.f;
        int   c = (tid < 16) ? sRc[tid] : 0;
        int   i = (tid < 16) ? sRi[tid] : 0;
#pragma unroll
        for (int off = 8; off > 0; off >>= 1) {
            a += __shfl_down_sync(mask, a, off);
            c += __shfl_down_sync(mask, c, off);
            i |= __shfl_down_sync(mask, i, off);
        }
        if (tid == 0) {
            g_stotal[b * NSTRIP + strip] = a;
            g_scnt [b * NSTRIP + strip] = c;
            g_sinc [b * NSTRIP + strip] = i;
            __threadfence();
            int t = atomicAdd(&g_arrive, 1);
            sLast = (t == NB * NSTRIP - 1) ? 1 : 0;
        }
    }
    __syncthreads();

    // Fused finalize: last block computes the scalar loss.
    if (sLast && tid < NB) {
        float tot = 0.f; int c = 0, i = 0;
        for (int s = 0; s < NSTRIP; s++) {
            tot += g_stotal[tid * NSTRIP + s];
            c   += g_scnt [tid * NSTRIP + s];
            i   |= g_sinc [tid * NSTRIP + s];
        }
        float li = i ? (tot / fmaxf((float)c, 1.f) / 24.f) : 0.f;
        unsigned m8 = 0xFFu;
        int sn = i ? 1 : 0;
#pragma unroll
        for (int off = 4; off > 0; off >>= 1) {
            li += __shfl_down_sync(m8, li, off);
            sn += __shfl_down_sync(m8, sn, off);
        }
        if (tid == 0) {
            out[0] = li / (float)(sn > 0 ? sn : 1);
            g_arrive = 0;   // reset for next graph replay
        }
    }
}

extern "C" void kernel_launch(void* const* d_in, const int* in_sizes, int n_in,
                              void* d_out, int out_size) {
    const float* er  = (const float*)d_in[0];
    const int*   seg = (const int*)d_in[1];
    const int*   gtb = (const int*)d_in[2];

    dim3 gridP(NH / 4, NB, CSPLIT);     // 32 x 8 x 4 = 1024 blocks
    partial_kernel<<<gridP, 128>>>(er);
    dim3 gridE(NSTRIP, NB);             // 32 x 8 = 256 blocks
    epilogue_kernel<<<gridE, 512>>>(seg, gtb, (float*)d_out);
}